// round 4
// baseline (speedup 1.0000x reference)
#include <cuda_runtime.h>
#include <cuda_bf16.h>
#include <stdint.h>

// ============================================================================
// PoolingRetriever: softmax over a length-1 sequence axis is identically 1,
// so the whole model reduces to:
//     out = (x @ Wv^T + bv) @ Wo^T + bo
// Two chained GEMMs. Toolchain targets sm_103 (no 'a' features): tcgen05/TMEM
// unavailable, so this uses warp-level mma.sync (HMMA) bf16 with fp32
// accumulate, with a bf16 hi/lo split (3 MMA passes) for fp32-level accuracy.
// All-register dataflow: no shared memory, no barriers; weights are
// pre-split + fragment-ordered by a prep kernel so B loads are single
// coalesced LDG.128s that stay L1-resident.
// ============================================================================

#define DIMK 768
#define RDIM 64
#define MT   128   // rows per CTA = 8 warps x 16

// Fragment-ordered weights: one uint4 per (fragment, lane):
//   .x = bf16x2 hi (k, k+1)   .y = bf16x2 hi (k+8, k+9)
//   .z = bf16x2 lo (k, k+1)   .w = bf16x2 lo (k+8, k+9)
// g_wv: [ch(12)][s(4)][j(8)][lane(32)]   (GEMM1: n = 8j + lane/4, k = 64ch+16s+2(lane%4))
// g_wo: [s(4)][jg(96)][lane(32)]         (GEMM2: n = 8jg + lane/4, k = 16s+2(lane%4))
__device__ uint4 g_wv[12 * 4 * 8 * 32];
__device__ uint4 g_wo[4 * 96 * 32];

// ---------------------------------------------------------------- helpers ---
static __device__ __forceinline__ void split2(float f0, float f1,
                                              uint32_t& hi, uint32_t& lo) {
    __nv_bfloat16 h0 = __float2bfloat16(f0);
    __nv_bfloat16 h1 = __float2bfloat16(f1);
    float r0 = f0 - __bfloat162float(h0);
    float r1 = f1 - __bfloat162float(h1);
    __nv_bfloat16 l0 = __float2bfloat16(r0);
    __nv_bfloat16 l1 = __float2bfloat16(r1);
    hi = (uint32_t)__bfloat16_as_ushort(h0) | ((uint32_t)__bfloat16_as_ushort(h1) << 16);
    lo = (uint32_t)__bfloat16_as_ushort(l0) | ((uint32_t)__bfloat16_as_ushort(l1) << 16);
}

#define MMA16816(C, A0, A1, A2, A3, B0, B1)                                   \
    asm volatile(                                                             \
        "mma.sync.aligned.m16n8k16.row.col.f32.bf16.bf16.f32 "                \
        "{%0,%1,%2,%3}, {%4,%5,%6,%7}, {%8,%9}, {%0,%1,%2,%3};"               \
        : "+f"((C)[0]), "+f"((C)[1]), "+f"((C)[2]), "+f"((C)[3])              \
        : "r"(A0), "r"(A1), "r"(A2), "r"(A3), "r"(B0), "r"(B1))

// ---------------------------------------------------------- weight prep -----
// 24576 uint4 entries total: first 12288 -> g_wv, rest -> g_wo.
__global__ void pr_prep_kernel(const float* __restrict__ Wv,
                               const float* __restrict__ Wo) {
    int i = blockIdx.x * blockDim.x + threadIdx.x;
    if (i >= 24576) return;
    int lane = i & 31;
    int q = lane & 3;        // lane % 4
    int nr = lane >> 2;      // lane / 4
    if (i < 12288) {
        int t = i >> 5;              // (ch*4 + s)*8 + j
        int j  = t & 7;
        int s  = (t >> 3) & 3;
        int ch = t >> 5;
        int n = 8 * j + nr;                       // 0..63
        int k = 64 * ch + 16 * s + 2 * q;         // 0..767
        const float* wr = Wv + (size_t)n * DIMK + k;
        uint32_t h01, l01, h23, l23;
        split2(wr[0], wr[1], h01, l01);
        split2(wr[8], wr[9], h23, l23);
        g_wv[i] = make_uint4(h01, h23, l01, l23);
    } else {
        int ii = i - 12288;
        int t = ii >> 5;             // s*96 + jg
        int jg = t % 96;
        int s  = t / 96;
        int n = 8 * jg + nr;                      // 0..767
        int k = 16 * s + 2 * q;                   // 0..63
        const float* wr = Wo + (size_t)n * RDIM + k;
        uint32_t h01, l01, h23, l23;
        split2(wr[0], wr[1], h01, l01);
        split2(wr[8], wr[9], h23, l23);
        g_wo[ii] = make_uint4(h01, h23, l01, l23);
    }
}

// -------------------------------------------------------------- main kernel -
__global__ void __launch_bounds__(256)
pr_main_kernel(const float* __restrict__ x, const float* __restrict__ bv,
               const float* __restrict__ bo, float* __restrict__ out) {
    const int tid  = threadIdx.x;
    const int w    = tid >> 5;
    const int lane = tid & 31;
    const int q    = lane & 3;
    const int nr   = lane >> 2;

    const int r0 = blockIdx.x * MT + w * 16 + nr;    // rows r0 and r0+8
    const float* xr0 = x + (size_t)r0 * DIMK;
    const float* xr1 = xr0 + 8 * DIMK;

    // ---------------- GEMM1: v(16x64 per warp) = x @ Wv^T -------------------
    float acc[8][4];
#pragma unroll
    for (int j = 0; j < 8; ++j)
#pragma unroll
        for (int c = 0; c < 4; ++c) acc[j][c] = 0.0f;

#pragma unroll 1
    for (int ch = 0; ch < 12; ++ch) {
#pragma unroll
        for (int s = 0; s < 4; ++s) {
            const int kb = ch * 64 + s * 16 + 2 * q;
            float2 f00 = __ldg((const float2*)(xr0 + kb));
            float2 f10 = __ldg((const float2*)(xr1 + kb));
            float2 f01 = __ldg((const float2*)(xr0 + kb + 8));
            float2 f11 = __ldg((const float2*)(xr1 + kb + 8));
            uint32_t ah0, al0, ah1, al1, ah2, al2, ah3, al3;
            split2(f00.x, f00.y, ah0, al0);   // a0: (r0, k..k+1)
            split2(f10.x, f10.y, ah1, al1);   // a1: (r0+8, k..k+1)
            split2(f01.x, f01.y, ah2, al2);   // a2: (r0, k+8..k+9)
            split2(f11.x, f11.y, ah3, al3);   // a3: (r0+8, k+8..k+9)
            const uint4* bp = g_wv + ((ch * 4 + s) * 8) * 32 + lane;
#pragma unroll
            for (int j = 0; j < 8; ++j) {
                uint4 b = __ldg(bp + j * 32);
                MMA16816(acc[j], ah0, ah1, ah2, ah3, b.x, b.y);   // hi*hi
                MMA16816(acc[j], al0, al1, al2, al3, b.x, b.y);   // lo*hi
                MMA16816(acc[j], ah0, ah1, ah2, ah3, b.z, b.w);   // hi*lo
            }
        }
    }

    // ---------------- v epilogue: +bv, re-split hi/lo into A-fragments ------
    // C-fragment cols of tile j are 8j+2q+{0,1}; A-fragment for GEMM2 kstep s2
    // needs k = 16*s2 + 2q (+8) -> tiles j = 2*s2 (regs 0,1) and 2*s2+1 (2,3).
    uint32_t vhi[4][4], vlo[4][4];
#pragma unroll
    for (int j = 0; j < 8; ++j) {
        float2 bvj = __ldg((const float2*)(bv + 8 * j + 2 * q));
        float f0 = acc[j][0] + bvj.x;
        float f1 = acc[j][1] + bvj.y;
        float f2 = acc[j][2] + bvj.x;   // row r0+8, same cols
        float f3 = acc[j][3] + bvj.y;
        int s2 = j >> 1;
        int h  = j & 1;
        split2(f0, f1, vhi[s2][2 * h + 0], vlo[s2][2 * h + 0]);
        split2(f2, f3, vhi[s2][2 * h + 1], vlo[s2][2 * h + 1]);
    }

    // ---------------- GEMM2: out(16x768 per warp) = v @ Wo^T + bo -----------
    float* outr0 = out + (size_t)r0 * DIMK;
#pragma unroll 1
    for (int nch = 0; nch < 12; ++nch) {
        float acc2[8][4];
#pragma unroll
        for (int j = 0; j < 8; ++j)
#pragma unroll
            for (int c = 0; c < 4; ++c) acc2[j][c] = 0.0f;

#pragma unroll
        for (int s2 = 0; s2 < 4; ++s2) {
            const uint4* bp = g_wo + (s2 * 96 + nch * 8) * 32 + lane;
#pragma unroll
            for (int j2 = 0; j2 < 8; ++j2) {
                uint4 b = __ldg(bp + j2 * 32);
                MMA16816(acc2[j2], vhi[s2][0], vhi[s2][1], vhi[s2][2], vhi[s2][3], b.x, b.y);
                MMA16816(acc2[j2], vlo[s2][0], vlo[s2][1], vlo[s2][2], vlo[s2][3], b.x, b.y);
                MMA16816(acc2[j2], vhi[s2][0], vhi[s2][1], vhi[s2][2], vhi[s2][3], b.z, b.w);
            }
        }
#pragma unroll
        for (int j2 = 0; j2 < 8; ++j2) {
            int c = nch * 64 + 8 * j2 + 2 * q;
            float2 bo2 = __ldg((const float2*)(bo + c));
            float2 o0 = make_float2(acc2[j2][0] + bo2.x, acc2[j2][1] + bo2.y);
            float2 o1 = make_float2(acc2[j2][2] + bo2.x, acc2[j2][3] + bo2.y);
            *(float2*)(outr0 + c) = o0;
            *(float2*)(outr0 + 8 * DIMK + c) = o1;
        }
    }
}

// ---------------------------------------------------------------- launch ----
extern "C" void kernel_launch(void* const* d_in, const int* in_sizes, int n_in,
                              void* d_out, int out_size) {
    const float* x  = (const float*)d_in[0];
    const float* Wv = (const float*)d_in[6];
    const float* bv = (const float*)d_in[7];
    const float* Wo = (const float*)d_in[8];
    const float* bo = (const float*)d_in[9];
    float* out = (float*)d_out;
    int nrows = in_sizes[0] / DIMK;   // 65536

    pr_prep_kernel<<<96, 256>>>(Wv, Wo);
    pr_main_kernel<<<nrows / MT, 256>>>(x, bv, bo, out);
}

// round 5
// speedup vs baseline: 1.4331x; 1.4331x over previous
#include <cuda_runtime.h>
#include <cuda_bf16.h>
#include <stdint.h>

// ============================================================================
// PoolingRetriever: softmax over a length-1 sequence axis is identically 1,
// so the whole model reduces to:
//     out = (x @ Wv^T + bv) @ Wo^T + bo
// Warp-level mma.sync (HMMA) bf16 + fp32 accumulate, bf16 hi/lo 3-pass split
// for fp32-level accuracy. All-register dataflow, no SMEM, no barriers.
// R5: 32 rows/warp (2x B-fragment reuse + 2x MMA ILP), double-buffered
// register prefetch of x, 64-thread CTAs for load balance.
// ============================================================================

#define DIMK 768
#define RDIM 64

// Fragment-ordered weights: one uint4 per (fragment, lane):
//   .x = bf16x2 hi (k, k+1)   .y = bf16x2 hi (k+8, k+9)
//   .z = bf16x2 lo (k, k+1)   .w = bf16x2 lo (k+8, k+9)
// g_wv: [ch(12)][s(4)][j(8)][lane(32)]   (n = 8j + lane/4, k = 64ch+16s+2(lane%4))
// g_wo: [s(4)][jg(96)][lane(32)]         (n = 8jg + lane/4, k = 16s+2(lane%4))
__device__ uint4 g_wv[12 * 4 * 8 * 32];
__device__ uint4 g_wo[4 * 96 * 32];

// ---------------------------------------------------------------- helpers ---
static __device__ __forceinline__ void split2(float f0, float f1,
                                              uint32_t& hi, uint32_t& lo) {
    __nv_bfloat16 h0 = __float2bfloat16(f0);
    __nv_bfloat16 h1 = __float2bfloat16(f1);
    float r0 = f0 - __bfloat162float(h0);
    float r1 = f1 - __bfloat162float(h1);
    __nv_bfloat16 l0 = __float2bfloat16(r0);
    __nv_bfloat16 l1 = __float2bfloat16(r1);
    hi = (uint32_t)__bfloat16_as_ushort(h0) | ((uint32_t)__bfloat16_as_ushort(h1) << 16);
    lo = (uint32_t)__bfloat16_as_ushort(l0) | ((uint32_t)__bfloat16_as_ushort(l1) << 16);
}

#define MMA16816(C, A0, A1, A2, A3, B0, B1)                                   \
    asm volatile(                                                             \
        "mma.sync.aligned.m16n8k16.row.col.f32.bf16.bf16.f32 "                \
        "{%0,%1,%2,%3}, {%4,%5,%6,%7}, {%8,%9}, {%0,%1,%2,%3};"               \
        : "+f"((C)[0]), "+f"((C)[1]), "+f"((C)[2]), "+f"((C)[3])              \
        : "r"(A0), "r"(A1), "r"(A2), "r"(A3), "r"(B0), "r"(B1))

// ---------------------------------------------------------- weight prep -----
__global__ void pr_prep_kernel(const float* __restrict__ Wv,
                               const float* __restrict__ Wo) {
    int i = blockIdx.x * blockDim.x + threadIdx.x;
    if (i >= 24576) return;
    int lane = i & 31;
    int q = lane & 3;
    int nr = lane >> 2;
    if (i < 12288) {
        int t = i >> 5;
        int j  = t & 7;
        int s  = (t >> 3) & 3;
        int ch = t >> 5;
        int n = 8 * j + nr;
        int k = 64 * ch + 16 * s + 2 * q;
        const float* wr = Wv + (size_t)n * DIMK + k;
        uint32_t h01, l01, h23, l23;
        split2(wr[0], wr[1], h01, l01);
        split2(wr[8], wr[9], h23, l23);
        g_wv[i] = make_uint4(h01, h23, l01, l23);
    } else {
        int ii = i - 12288;
        int t = ii >> 5;
        int jg = t % 96;
        int s  = t / 96;
        int n = 8 * jg + nr;
        int k = 16 * s + 2 * q;
        const float* wr = Wo + (size_t)n * RDIM + k;
        uint32_t h01, l01, h23, l23;
        split2(wr[0], wr[1], h01, l01);
        split2(wr[8], wr[9], h23, l23);
        g_wo[ii] = make_uint4(h01, h23, l01, l23);
    }
}

// -------------------------------------------------------------- main kernel -
// 64 threads = 2 warps per CTA; each warp owns 32 rows (two 16-row MMA pairs).
__global__ void __launch_bounds__(64)
pr_main_kernel(const float* __restrict__ x, const float* __restrict__ bv,
               const float* __restrict__ bo, float* __restrict__ out) {
    const int tid  = threadIdx.x;
    const int w    = tid >> 5;
    const int lane = tid & 31;
    const int q    = lane & 3;
    const int nr   = lane >> 2;

    const int r0 = blockIdx.x * 64 + w * 32 + nr;
    const float* xp0 = x + (size_t)r0 * DIMK;           // rows r0,   r0+8  (pair0)
    const float* xp1 = xp0 + 8 * DIMK;
    const float* xp2 = xp0 + 16 * DIMK;                 // rows r0+16,r0+24 (pair1)
    const float* xp3 = xp0 + 24 * DIMK;

    // ---------------- GEMM1: v(32x64 per warp) = x @ Wv^T -------------------
    float acc[8][8];
#pragma unroll
    for (int j = 0; j < 8; ++j)
#pragma unroll
        for (int c = 0; c < 8; ++c) acc[j][c] = 0.0f;

    float2 xf[2][8];
#define LOADX(buf, ch, s)                                                     \
    do {                                                                      \
        const int kb_ = (ch) * 64 + (s) * 16 + 2 * q;                         \
        xf[buf][0] = __ldg((const float2*)(xp0 + kb_));                       \
        xf[buf][1] = __ldg((const float2*)(xp1 + kb_));                       \
        xf[buf][2] = __ldg((const float2*)(xp0 + kb_ + 8));                   \
        xf[buf][3] = __ldg((const float2*)(xp1 + kb_ + 8));                   \
        xf[buf][4] = __ldg((const float2*)(xp2 + kb_));                       \
        xf[buf][5] = __ldg((const float2*)(xp3 + kb_));                       \
        xf[buf][6] = __ldg((const float2*)(xp2 + kb_ + 8));                   \
        xf[buf][7] = __ldg((const float2*)(xp3 + kb_ + 8));                   \
    } while (0)

    LOADX(0, 0, 0);

#pragma unroll 1
    for (int ch = 0; ch < 12; ++ch) {
#pragma unroll
        for (int s = 0; s < 4; ++s) {
            const int cur = s & 1;
            uint32_t ah[8], al[8];
#pragma unroll
            for (int i = 0; i < 8; ++i)
                split2(xf[cur][i].x, xf[cur][i].y, ah[i], al[i]);
            // prefetch next k-step (hides DRAM latency behind the 48 MMAs)
            if (s < 3)           LOADX(1 - cur, ch, s + 1);
            else if (ch < 11)    LOADX(1 - cur, ch + 1, 0);

            const uint4* bp = g_wv + ((ch * 4 + s) * 8) * 32 + lane;
#pragma unroll
            for (int j = 0; j < 8; ++j) {
                uint4 b = __ldg(bp + j * 32);
                MMA16816(acc[j] + 0, ah[0], ah[1], ah[2], ah[3], b.x, b.y);
                MMA16816(acc[j] + 4, ah[4], ah[5], ah[6], ah[7], b.x, b.y);
                MMA16816(acc[j] + 0, al[0], al[1], al[2], al[3], b.x, b.y);
                MMA16816(acc[j] + 4, al[4], al[5], al[6], al[7], b.x, b.y);
                MMA16816(acc[j] + 0, ah[0], ah[1], ah[2], ah[3], b.z, b.w);
                MMA16816(acc[j] + 4, ah[4], ah[5], ah[6], ah[7], b.z, b.w);
            }
        }
    }
#undef LOADX

    // ---------------- v epilogue: +bv, re-split hi/lo into A-fragments ------
    // Tile j covers cols 8j+2q(+1); GEMM2 k-step s2 wants k = 16*s2+2q (+8)
    // -> tiles j=2*s2 (frag regs 0,1) and j=2*s2+1 (frag regs 2,3).
    uint32_t vhi[4][4], vlo[4][4];     // pair0 (rows r0..r0+15)
    uint32_t uhi[4][4], ulo[4][4];     // pair1 (rows r0+16..r0+31)
#pragma unroll
    for (int j = 0; j < 8; ++j) {
        float2 bvj = __ldg((const float2*)(bv + 8 * j + 2 * q));
        int s2 = j >> 1, h = j & 1;
        split2(acc[j][0] + bvj.x, acc[j][1] + bvj.y, vhi[s2][2 * h + 0], vlo[s2][2 * h + 0]);
        split2(acc[j][2] + bvj.x, acc[j][3] + bvj.y, vhi[s2][2 * h + 1], vlo[s2][2 * h + 1]);
        split2(acc[j][4] + bvj.x, acc[j][5] + bvj.y, uhi[s2][2 * h + 0], ulo[s2][2 * h + 0]);
        split2(acc[j][6] + bvj.x, acc[j][7] + bvj.y, uhi[s2][2 * h + 1], ulo[s2][2 * h + 1]);
    }

    // ---------------- GEMM2: out(32x768 per warp) = v @ Wo^T + bo -----------
    float* op0 = out + (size_t)r0 * DIMK;
    float* op1 = op0 + 8 * DIMK;
    float* op2 = op0 + 16 * DIMK;
    float* op3 = op0 + 24 * DIMK;

#pragma unroll 1
    for (int nc = 0; nc < 24; ++nc) {          // 24 col-chunks of 32
        float acc2[4][8];
#pragma unroll
        for (int j2 = 0; j2 < 4; ++j2)
#pragma unroll
            for (int c = 0; c < 8; ++c) acc2[j2][c] = 0.0f;

#pragma unroll
        for (int s2 = 0; s2 < 4; ++s2) {
            const uint4* bp = g_wo + (s2 * 96 + nc * 4) * 32 + lane;
#pragma unroll
            for (int j2 = 0; j2 < 4; ++j2) {
                uint4 b = __ldg(bp + j2 * 32);
                MMA16816(acc2[j2] + 0, vhi[s2][0], vhi[s2][1], vhi[s2][2], vhi[s2][3], b.x, b.y);
                MMA16816(acc2[j2] + 4, uhi[s2][0], uhi[s2][1], uhi[s2][2], uhi[s2][3], b.x, b.y);
                MMA16816(acc2[j2] + 0, vlo[s2][0], vlo[s2][1], vlo[s2][2], vlo[s2][3], b.x, b.y);
                MMA16816(acc2[j2] + 4, ulo[s2][0], ulo[s2][1], ulo[s2][2], ulo[s2][3], b.x, b.y);
                MMA16816(acc2[j2] + 0, vhi[s2][0], vhi[s2][1], vhi[s2][2], vhi[s2][3], b.z, b.w);
                MMA16816(acc2[j2] + 4, uhi[s2][0], uhi[s2][1], uhi[s2][2], uhi[s2][3], b.z, b.w);
            }
        }
#pragma unroll
        for (int j2 = 0; j2 < 4; ++j2) {
            int c = nc * 32 + 8 * j2 + 2 * q;
            float2 bo2 = __ldg((const float2*)(bo + c));
            *(float2*)(op0 + c) = make_float2(acc2[j2][0] + bo2.x, acc2[j2][1] + bo2.y);
            *(float2*)(op1 + c) = make_float2(acc2[j2][2] + bo2.x, acc2[j2][3] + bo2.y);
            *(float2*)(op2 + c) = make_float2(acc2[j2][4] + bo2.x, acc2[j2][5] + bo2.y);
            *(float2*)(op3 + c) = make_float2(acc2[j2][6] + bo2.x, acc2[j2][7] + bo2.y);
        }
    }
}

// ---------------------------------------------------------------- launch ----
extern "C" void kernel_launch(void* const* d_in, const int* in_sizes, int n_in,
                              void* d_out, int out_size) {
    const float* x  = (const float*)d_in[0];
    const float* Wv = (const float*)d_in[6];
    const float* bv = (const float*)d_in[7];
    const float* Wo = (const float*)d_in[8];
    const float* bo = (const float*)d_in[9];
    float* out = (float*)d_out;
    int nrows = in_sizes[0] / DIMK;   // 65536

    pr_prep_kernel<<<96, 256>>>(Wv, Wo);
    pr_main_kernel<<<nrows / 64, 64>>>(x, bv, bo, out);
}